// round 1
// baseline (speedup 1.0000x reference)
#include <cuda_runtime.h>
#include <cmath>

#define NUM_S 7
#define NUM_R 6
#define MAX_EDGES 200000
#define RBF_STRIDE 56   // 7 l-groups padded to 8 floats each

// Per-edge precomputed radial basis, padded layout [e][l][8] (j=0..5 valid).
__device__ float g_rbf[(size_t)MAX_EDGES * RBF_STRIDE];

// l index for each of the 49 sph-harm columns (l repeated 2l+1 times)
__constant__ int c_LIDX[49] = {
    0,
    1,1,1,
    2,2,2,2,2,
    3,3,3,3,3,3,3,
    4,4,4,4,4,4,4,4,4,
    5,5,5,5,5,5,5,5,5,5,5,
    6,6,6,6,6,6,6,6,6,6,6,6,6
};

struct K1Params { float Z[NUM_S][NUM_R]; float C[NUM_S][NUM_R]; };  // C = BNORM * cutoff^-1.5
struct K2Params { float CK[NUM_S][NUM_S]; };                        // K(l,m) (* sqrt2 for m>0)

// ---------------- host-side constant computation (pure CPU, double) ----------------
static double sph_jn_d(int n, double x) {
    double j0 = sin(x) / x;
    if (n == 0) return j0;
    double j1 = sin(x) / (x * x) - cos(x) / x;
    double jm1 = j0, jc = j1;
    for (int l = 1; l < n; l++) {
        double t = (2.0 * l + 1.0) / x * jc - jm1;
        jm1 = jc; jc = t;
    }
    return jc;
}

struct HostConsts { K1Params p1; K2Params p2; };

static HostConsts compute_consts() {
    const double PI = 3.14159265358979323846;
    double Z[NUM_S][NUM_R];
    double points[NUM_S + NUM_R];
    for (int k = 0; k < NUM_R; k++) Z[0][k] = (k + 1) * PI;
    int npts = NUM_R + NUM_S - 1;                 // 12
    for (int i = 0; i < npts; i++) points[i] = (i + 1) * PI;
    double racines[NUM_S + NUM_R];
    for (int order = 1; order < NUM_S; order++) {
        int nroots = NUM_R + NUM_S - 1 - order;
        for (int j = 0; j < nroots; j++) {
            double a = points[j], b = points[j + 1];
            double fa = sph_jn_d(order, a);
            for (int it = 0; it < 80; it++) {
                double m = 0.5 * (a + b);
                double fm = sph_jn_d(order, m);
                if (fa * fm <= 0.0) b = m; else { a = m; fa = fm; }
            }
            racines[j] = 0.5 * (a + b);
        }
        for (int i = 0; i < nroots; i++) points[i] = racines[i];
        for (int k = 0; k < NUM_R; k++) Z[order][k] = racines[k];
    }
    HostConsts h;
    double norm_const = pow(1.0 / 5.0, 1.5);
    for (int l = 0; l < NUM_S; l++)
        for (int j = 0; j < NUM_R; j++) {
            double bn = 1.0 / sqrt(0.5 * sph_jn_d(l + 1, Z[l][j]) * sph_jn_d(l + 1, Z[l][j]));
            h.p1.Z[l][j] = (float)Z[l][j];
            h.p1.C[l][j] = (float)(bn * norm_const);
        }
    double fact[16]; fact[0] = 1.0;
    for (int i = 1; i < 16; i++) fact[i] = fact[i - 1] * i;
    for (int l = 0; l < NUM_S; l++)
        for (int m = 0; m <= l; m++) {
            double K = sqrt((2.0 * l + 1.0) / (4.0 * PI) * fact[l - m] / fact[l + m]);
            if (m > 0) K *= sqrt(2.0);
            h.p2.CK[l][m] = (float)K;
        }
    return h;
}

static const HostConsts& host_consts() {
    static HostConsts h = compute_consts();   // CPU-only init; device work identical every call
    return h;
}

// ---------------- kernel 1: per-edge radial basis (42 values, padded to 56) ----------------
__global__ __launch_bounds__(256)
void k1_kernel(const float* __restrict__ D, int NE, K1Params P) {
    int e = blockIdx.x * blockDim.x + threadIdx.x;
    if (e >= NE) return;
    float d = D[e] * 0.2f;                    // D / CUTOFF
    float u;
    {
        float invd = 1.0f / d;
        float d2 = d * d, d4 = d2 * d2, d5 = d4 * d;
        u = invd + d5 * (-28.0f + d * (48.0f - 21.0f * d));
        if (!(d < 1.0f)) u = 0.0f;
    }
    float o[RBF_STRIDE];
#pragma unroll
    for (int l = 0; l < NUM_S; l++) {
#pragma unroll
        for (int j = 0; j < NUM_R; j++) {
            float x = d * P.Z[l][j];
            float s, c;
            sincosf(x, &s, &c);
            float invx = 1.0f / x;
            float cur = s * invx;             // j0
            if (l >= 1) {
                float prev = cur;
                cur = s * invx * invx - c * invx;   // j1 (same form as reference)
#pragma unroll
                for (int k = 1; k < l; k++) {
                    float nx = (2.0f * k + 1.0f) * invx * cur - prev;
                    prev = cur; cur = nx;
                }
            }
            o[l * 8 + j] = u * P.C[l][j] * cur;
        }
        o[l * 8 + 6] = 0.0f;
        o[l * 8 + 7] = 0.0f;
    }
    float4* dst = (float4*)(g_rbf + (size_t)e * RBF_STRIDE);
#pragma unroll
    for (int w = 0; w < 14; w++) dst[w] = ((float4*)o)[w];
}

// ---------------- kernel 2: sph harm + gather + 470MB streaming write ----------------
#define QPB 128
#define K2_SMEM (QPB * RBF_STRIDE * 4 + QPB * 49 * 4 + QPB * 4)   // 54272 B

__global__ __launch_bounds__(QPB)
void k2_kernel(const float* __restrict__ Alpha, const float* __restrict__ Theta,
               const int* __restrict__ id4, float* __restrict__ out,
               int NQ, K2Params P) {
    extern __shared__ __align__(16) float smem[];
    float* rbf_s = smem;                       // [QPB][56], 16B aligned rows
    float* sph_s = smem + QPB * RBF_STRIDE;    // [QPB][49]
    int*   e_s   = (int*)(sph_s + QPB * 49);   // [QPB]

    int t = threadIdx.x;
    int q0 = blockIdx.x * QPB;
    int nq = min(QPB, NQ - q0);

    if (t < nq) e_s[t] = id4[q0 + t];
    __syncthreads();

    // cooperative gather of rbf rows (float4, L2-resident)
    {
        int tot4 = nq * 14;
        const float4* src = (const float4*)g_rbf;
        float4* dst = (float4*)rbf_s;
        for (int i = t; i < tot4; i += QPB) {
            int q = i / 14, w = i - q * 14;
            dst[q * 14 + w] = src[(size_t)e_s[q] * 14 + w];
        }
    }

    // each thread computes the 49 sph-harm values for one quad
    if (t < nq) {
        float th = Alpha[q0 + t], ph = Theta[q0 + t];
        float st_, ct_;
        sincosf(th, &st_, &ct_);
        float* sp = sph_s + t * 49;
        float pmm = 1.0f;
#pragma unroll
        for (int m = 0; m < NUM_S; m++) {
            float cm, sm;
            if (m == 0) { cm = 1.0f; sm = 0.0f; }
            else sincosf((float)m * ph, &sm, &cm);
            float pa = pmm;
            {   // l = m
                int l = m;
                float k = P.CK[l][m];
                if (m == 0) sp[l * l] = k * pa;
                else { sp[l * l + m] = k * cm * pa; sp[(l + 1) * (l + 1) - m] = k * sm * pa; }
            }
            if (m < NUM_S - 1) {
                float pb = (2.0f * m + 1.0f) * ct_ * pa;
                {   // l = m+1
                    int l = m + 1;
                    float k = P.CK[l][m];
                    if (m == 0) sp[l * l] = k * pb;
                    else { sp[l * l + m] = k * cm * pb; sp[(l + 1) * (l + 1) - m] = k * sm * pb; }
                }
#pragma unroll
                for (int l = m + 2; l < NUM_S; l++) {
                    float pc = ((2.0f * l - 1.0f) * ct_ * pb - (float)(l + m - 1) * pa) / (float)(l - m);
                    pa = pb; pb = pc;
                    float k = P.CK[l][m];
                    if (m == 0) sp[l * l] = k * pc;
                    else { sp[l * l + m] = k * cm * pc; sp[(l + 1) * (l + 1) - m] = k * sm * pc; }
                }
            }
            pmm = (1.0f - 2.0f * (m + 1)) * st_ * pmm;
        }
    }
    __syncthreads();

    // phase B: write 294 floats per quad. Process pairs of 6-float groups
    // -> 48B per iteration, 16B aligned -> 3x STG.128 (streaming).
    int total = nq * 49;
    int npair = total >> 1;
    for (int pi = t; pi < npair; pi += QPB) {
        int g0 = pi << 1;
        float v[12];
#pragma unroll
        for (int h = 0; h < 2; h++) {
            int g = g0 + h;
            int q = g / 49;
            int c = g - q * 49;
            int l = c_LIDX[c];
            float s = sph_s[q * 49 + c];
            const float* rp = rbf_s + q * RBF_STRIDE + l * 8;
            float4 r0 = *(const float4*)rp;
            float2 r1 = *(const float2*)(rp + 4);
            v[h * 6 + 0] = s * r0.x; v[h * 6 + 1] = s * r0.y;
            v[h * 6 + 2] = s * r0.z; v[h * 6 + 3] = s * r0.w;
            v[h * 6 + 4] = s * r1.x; v[h * 6 + 5] = s * r1.y;
        }
        float4* dst = (float4*)(out + ((size_t)q0 * 49 + (size_t)g0) * 6);
        __stcs(dst + 0, make_float4(v[0], v[1], v[2],  v[3]));
        __stcs(dst + 1, make_float4(v[4], v[5], v[6],  v[7]));
        __stcs(dst + 2, make_float4(v[8], v[9], v[10], v[11]));
    }
    if ((total & 1) && t == 0) {
        int g = total - 1;
        int q = g / 49, c = g - q * 49;
        int l = c_LIDX[c];
        float s = sph_s[q * 49 + c];
        const float* rp = rbf_s + q * RBF_STRIDE + l * 8;
        float* dst = out + ((size_t)q0 * 49 + (size_t)g) * 6;
#pragma unroll
        for (int j = 0; j < 6; j++) dst[j] = s * rp[j];
    }
}

extern "C" void kernel_launch(void* const* d_in, const int* in_sizes, int n_in,
                              void* d_out, int out_size) {
    const float* D   = (const float*)d_in[0];
    const float* Al  = (const float*)d_in[1];
    const float* Th  = (const float*)d_in[2];
    const int*   id4 = (const int*)d_in[3];
    float* out = (float*)d_out;
    int NE = in_sizes[0];
    int NQ = in_sizes[1];
    if (NE > MAX_EDGES) NE = MAX_EDGES;

    const HostConsts& H = host_consts();

    cudaFuncSetAttribute(k2_kernel, cudaFuncAttributeMaxDynamicSharedMemorySize, K2_SMEM);

    k1_kernel<<<(NE + 255) / 256, 256>>>(D, NE, H.p1);
    k2_kernel<<<(NQ + QPB - 1) / QPB, QPB, K2_SMEM>>>(Al, Th, id4, out, NQ, H.p2);
}

// round 2
// speedup vs baseline: 1.0938x; 1.0938x over previous
#include <cuda_runtime.h>
#include <cmath>

#define NUM_S 7
#define NUM_R 6
#define MAX_EDGES 200000
#define RBF_STRIDE 56   // 7 l-groups padded to 8 floats each

// Per-edge precomputed radial basis, padded layout [e][l][8] (j=0..5 valid).
__device__ float g_rbf[(size_t)MAX_EDGES * RBF_STRIDE];

// l index for each of the 49 sph-harm columns (l repeated 2l+1 times)
__constant__ int c_LIDX[49] = {
    0,
    1,1,1,
    2,2,2,2,2,
    3,3,3,3,3,3,3,
    4,4,4,4,4,4,4,4,4,
    5,5,5,5,5,5,5,5,5,5,5,
    6,6,6,6,6,6,6,6,6,6,6,6,6
};

struct K1Params { float Z[NUM_S][NUM_R]; float C[NUM_S][NUM_R]; };  // C = BNORM * cutoff^-1.5
struct K2Params { float CK[NUM_S][NUM_S]; };                        // K(l,m) (* sqrt2 for m>0)

// ---------------- host-side constant computation (pure CPU, double) ----------------
static double sph_jn_d(int n, double x) {
    double j0 = sin(x) / x;
    if (n == 0) return j0;
    double j1 = sin(x) / (x * x) - cos(x) / x;
    double jm1 = j0, jc = j1;
    for (int l = 1; l < n; l++) {
        double t = (2.0 * l + 1.0) / x * jc - jm1;
        jm1 = jc; jc = t;
    }
    return jc;
}

struct HostConsts { K1Params p1; K2Params p2; };

static HostConsts compute_consts() {
    const double PI = 3.14159265358979323846;
    double Z[NUM_S][NUM_R];
    double points[NUM_S + NUM_R];
    for (int k = 0; k < NUM_R; k++) Z[0][k] = (k + 1) * PI;
    int npts = NUM_R + NUM_S - 1;                 // 12
    for (int i = 0; i < npts; i++) points[i] = (i + 1) * PI;
    double racines[NUM_S + NUM_R];
    for (int order = 1; order < NUM_S; order++) {
        int nroots = NUM_R + NUM_S - 1 - order;
        for (int j = 0; j < nroots; j++) {
            double a = points[j], b = points[j + 1];
            double fa = sph_jn_d(order, a);
            for (int it = 0; it < 80; it++) {
                double m = 0.5 * (a + b);
                double fm = sph_jn_d(order, m);
                if (fa * fm <= 0.0) b = m; else { a = m; fa = fm; }
            }
            racines[j] = 0.5 * (a + b);
        }
        for (int i = 0; i < nroots; i++) points[i] = racines[i];
        for (int k = 0; k < NUM_R; k++) Z[order][k] = racines[k];
    }
    HostConsts h;
    double norm_const = pow(1.0 / 5.0, 1.5);
    for (int l = 0; l < NUM_S; l++)
        for (int j = 0; j < NUM_R; j++) {
            double bn = 1.0 / sqrt(0.5 * sph_jn_d(l + 1, Z[l][j]) * sph_jn_d(l + 1, Z[l][j]));
            h.p1.Z[l][j] = (float)Z[l][j];
            h.p1.C[l][j] = (float)(bn * norm_const);
        }
    double fact[16]; fact[0] = 1.0;
    for (int i = 1; i < 16; i++) fact[i] = fact[i - 1] * i;
    for (int l = 0; l < NUM_S; l++)
        for (int m = 0; m <= l; m++) {
            double K = sqrt((2.0 * l + 1.0) / (4.0 * PI) * fact[l - m] / fact[l + m]);
            if (m > 0) K *= sqrt(2.0);
            h.p2.CK[l][m] = (float)K;
        }
    return h;
}

static const HostConsts& host_consts() {
    static HostConsts h = compute_consts();   // CPU-only init; device work identical every call
    return h;
}

// ---------------- kernel 1: per-edge radial basis (42 values, padded to 56) ----------------
__global__ __launch_bounds__(256)
void k1_kernel(const float* __restrict__ D, int NE, K1Params P) {
    int e = blockIdx.x * blockDim.x + threadIdx.x;
    if (e >= NE) return;
    float d = D[e] * 0.2f;                    // D / CUTOFF
    float u;
    {
        float invd = 1.0f / d;
        float d2 = d * d, d4 = d2 * d2, d5 = d4 * d;
        u = invd + d5 * (-28.0f + d * (48.0f - 21.0f * d));
        if (!(d < 1.0f)) u = 0.0f;
    }
    float o[RBF_STRIDE];
#pragma unroll
    for (int l = 0; l < NUM_S; l++) {
#pragma unroll
        for (int j = 0; j < NUM_R; j++) {
            float x = d * P.Z[l][j];
            float s, c;
            sincosf(x, &s, &c);
            float invx = 1.0f / x;
            float cur = s * invx;             // j0
            if (l >= 1) {
                float prev = cur;
                cur = s * invx * invx - c * invx;   // j1 (same form as reference)
#pragma unroll
                for (int k = 1; k < l; k++) {
                    float nx = (2.0f * k + 1.0f) * invx * cur - prev;
                    prev = cur; cur = nx;
                }
            }
            o[l * 8 + j] = u * P.C[l][j] * cur;
        }
        o[l * 8 + 6] = 0.0f;
        o[l * 8 + 7] = 0.0f;
    }
    float4* dst = (float4*)(g_rbf + (size_t)e * RBF_STRIDE);
#pragma unroll
    for (int w = 0; w < 14; w++) dst[w] = ((float4*)o)[w];
}

// ---------------- kernel 2: sph harm + L2 gather + 470MB streaming write ----------------
#define QPB 128
// smem: sph [QPB][49] + edge idx [QPB]  -> 25.6 KB  => 8 CTAs/SM = 32 warps (50% occ)
#define K2_SMEM (QPB * 49 * 4 + QPB * 4)

__global__ __launch_bounds__(QPB)
void k2_kernel(const float* __restrict__ Alpha, const float* __restrict__ Theta,
               const int* __restrict__ id4, float* __restrict__ out,
               int NQ, K2Params P) {
    extern __shared__ __align__(16) float smem[];
    float* sph_s = smem;                       // [QPB][49]
    int*   e_s   = (int*)(sph_s + QPB * 49);   // [QPB]

    int t = threadIdx.x;
    int q0 = blockIdx.x * QPB;
    int nq = min(QPB, NQ - q0);

    if (t < nq) e_s[t] = id4[q0 + t];

    // each thread computes the 49 sph-harm values for one quad
    if (t < nq) {
        float th = Alpha[q0 + t], ph = Theta[q0 + t];
        float st_, ct_;
        sincosf(th, &st_, &ct_);
        float* sp = sph_s + t * 49;
        float pmm = 1.0f;
#pragma unroll
        for (int m = 0; m < NUM_S; m++) {
            float cm, sm;
            if (m == 0) { cm = 1.0f; sm = 0.0f; }
            else sincosf((float)m * ph, &sm, &cm);
            float pa = pmm;
            {   // l = m
                int l = m;
                float k = P.CK[l][m];
                if (m == 0) sp[l * l] = k * pa;
                else { sp[l * l + m] = k * cm * pa; sp[(l + 1) * (l + 1) - m] = k * sm * pa; }
            }
            if (m < NUM_S - 1) {
                float pb = (2.0f * m + 1.0f) * ct_ * pa;
                {   // l = m+1
                    int l = m + 1;
                    float k = P.CK[l][m];
                    if (m == 0) sp[l * l] = k * pb;
                    else { sp[l * l + m] = k * cm * pb; sp[(l + 1) * (l + 1) - m] = k * sm * pb; }
                }
#pragma unroll
                for (int l = m + 2; l < NUM_S; l++) {
                    float pc = ((2.0f * l - 1.0f) * ct_ * pb - (float)(l + m - 1) * pa) / (float)(l - m);
                    pa = pb; pb = pc;
                    float k = P.CK[l][m];
                    if (m == 0) sp[l * l] = k * pc;
                    else { sp[l * l + m] = k * cm * pc; sp[(l + 1) * (l + 1) - m] = k * sm * pc; }
                }
            }
            pmm = (1.0f - 2.0f * (m + 1)) * st_ * pmm;
        }
    }
    __syncthreads();

    // phase B: write 294 floats per quad. Pairs of 6-float groups -> 48B per
    // iteration, 16B aligned -> 3x STG.128 streaming. rbf groups are read
    // directly from L2-resident g_rbf (no smem staging -> 2x occupancy).
    int total = nq * 49;
    int npair = total >> 1;
    for (int pi = t; pi < npair; pi += QPB) {
        int g0 = pi << 1;
        float v[12];
#pragma unroll
        for (int h = 0; h < 2; h++) {
            int g = g0 + h;
            int q = g / 49;
            int c = g - q * 49;
            int l = c_LIDX[c];
            float s = sph_s[q * 49 + c];
            const float* rp = g_rbf + (size_t)e_s[q] * RBF_STRIDE + l * 8;
            float4 r0 = __ldg((const float4*)rp);
            float2 r1 = __ldg((const float2*)(rp + 4));
            v[h * 6 + 0] = s * r0.x; v[h * 6 + 1] = s * r0.y;
            v[h * 6 + 2] = s * r0.z; v[h * 6 + 3] = s * r0.w;
            v[h * 6 + 4] = s * r1.x; v[h * 6 + 5] = s * r1.y;
        }
        float4* dst = (float4*)(out + ((size_t)q0 * 49 + (size_t)g0) * 6);
        __stcs(dst + 0, make_float4(v[0], v[1], v[2],  v[3]));
        __stcs(dst + 1, make_float4(v[4], v[5], v[6],  v[7]));
        __stcs(dst + 2, make_float4(v[8], v[9], v[10], v[11]));
    }
    if ((total & 1) && t == 0) {
        int g = total - 1;
        int q = g / 49, c = g - q * 49;
        int l = c_LIDX[c];
        float s = sph_s[q * 49 + c];
        const float* rp = g_rbf + (size_t)e_s[q] * RBF_STRIDE + l * 8;
        float* dst = out + ((size_t)q0 * 49 + (size_t)g) * 6;
#pragma unroll
        for (int j = 0; j < 6; j++) dst[j] = s * rp[j];
    }
}

extern "C" void kernel_launch(void* const* d_in, const int* in_sizes, int n_in,
                              void* d_out, int out_size) {
    const float* D   = (const float*)d_in[0];
    const float* Al  = (const float*)d_in[1];
    const float* Th  = (const float*)d_in[2];
    const int*   id4 = (const int*)d_in[3];
    float* out = (float*)d_out;
    int NE = in_sizes[0];
    int NQ = in_sizes[1];
    if (NE > MAX_EDGES) NE = MAX_EDGES;

    const HostConsts& H = host_consts();

    k1_kernel<<<(NE + 255) / 256, 256>>>(D, NE, H.p1);
    k2_kernel<<<(NQ + QPB - 1) / QPB, QPB, K2_SMEM>>>(Al, Th, id4, out, NQ, H.p2);
}